// round 15
// baseline (speedup 1.0000x reference)
#include <cuda_runtime.h>
#include <cuda_fp16.h>
#include <cstdint>
#include <math.h>

#define N_NODES 50000
#define N_EDGES 800000
#define N_GRAPHS 500
#define C 16            // IN_C == HID_C == 16
#define OUT_C 10
#define MLP_HID 25
#define KROWS 26        // 25 MLP rows + 1 bias row (always weight 1)
#define PROW_PAD 448    // padded to 896 B = 7 x 128B lines per node
#define HROW 32         // padded h row: 32 halves = 64 B
#define SCAN_BLOCKS ((N_NODES + 255) / 256)   // 196

// ---------------- scratch (static device globals; no allocs allowed) ----------------
__device__ __align__(128) __half g_Ph[(size_t)N_NODES * PROW_PAD];   // 44.8 MB
__device__ __align__(128) __half g_h[(size_t)N_EDGES * HROW];        // 51.2 MB packed h
__device__ __align__(16) float g_aggA[N_NODES * C];
__device__ __align__(16) float g_aggB[N_NODES * C];
__device__ float g_deg[N_NODES];
__device__ __align__(16) float g_x1[N_NODES * C];
__device__ __align__(16) float g_pooled[N_GRAPHS * C];
__device__ float g_cnt[N_GRAPHS];
__device__ float g_sc1[2 * MLP_HID];
__device__ float g_sc2[2 * MLP_HID];
// edge sort scratch
__device__ int g_srccnt[N_NODES];
__device__ int g_cur[N_NODES];
__device__ int g_blocksum[SCAN_BLOCKS];
__device__ __align__(16) int4 g_e4[N_EDGES];    // {src, dst, a0bits, a1bits}
__device__ float g_ea2[N_EDGES];                // a2

// ---------------- zero scratch ----------------
__global__ void zero_kernel() {
    int t = blockIdx.x * blockDim.x + threadIdx.x;
    int stride = gridDim.x * blockDim.x;
    const int NA = N_NODES * C;
    for (int i = t; i < NA; i += stride) { g_aggA[i] = 0.f; g_aggB[i] = 0.f; }
    for (int i = t; i < N_NODES; i += stride) { g_deg[i] = 0.f; g_srccnt[i] = 0; }
    for (int i = t; i < N_GRAPHS * C; i += stride) g_pooled[i] = 0.f;
    for (int i = t; i < N_GRAPHS; i += stride) g_cnt[i] = 0.f;
}

// ---------------- fold BatchNorm(eval) into affine: h = relu(s*dot + c) ----------------
__global__ void prep_kernel(const float* __restrict__ b1a, const float* __restrict__ g1,
                            const float* __restrict__ bt1, const float* __restrict__ m1,
                            const float* __restrict__ v1,
                            const float* __restrict__ b2a, const float* __restrict__ g2,
                            const float* __restrict__ bt2, const float* __restrict__ m2,
                            const float* __restrict__ v2) {
    int k = threadIdx.x;
    if (k < MLP_HID) {
        float s1 = g1[k] * rsqrtf(v1[k] + 1e-5f);
        g_sc1[k] = s1;
        g_sc1[MLP_HID + k] = s1 * (b1a[k] - m1[k]) + bt1[k];
        float s2 = g2[k] * rsqrtf(v2[k] + 1e-5f);
        g_sc2[k] = s2;
        g_sc2[MLP_HID + k] = s2 * (b2a[k] - m2[k]) + bt2[k];
    }
}

// ---------------- counting sort of edges by src ----------------
__global__ void hist_kernel(const int* __restrict__ ei) {
    int t = blockIdx.x * blockDim.x + threadIdx.x;
    int stride = gridDim.x * blockDim.x;
    for (int e = t; e < N_EDGES; e += stride) {
        atomicAdd(&g_srccnt[__ldg(&ei[e])], 1);
        atomicAdd(&g_deg[__ldg(&ei[N_EDGES + e])], 1.0f);
    }
}

__global__ void scanA_kernel() {
    __shared__ int s[256];
    int t = threadIdx.x;
    int idx = blockIdx.x * 256 + t;
    int v = (idx < N_NODES) ? g_srccnt[idx] : 0;
    s[t] = v;
    __syncthreads();
    for (int off = 1; off < 256; off <<= 1) {
        int u = (t >= off) ? s[t - off] : 0;
        __syncthreads();
        s[t] += u;
        __syncthreads();
    }
    if (idx < N_NODES) g_cur[idx] = s[t] - v;
    if (t == 255) g_blocksum[blockIdx.x] = s[255];
}

__global__ void scanB_kernel() {
    __shared__ int s[256];
    int t = threadIdx.x;
    int v = (t < SCAN_BLOCKS) ? g_blocksum[t] : 0;
    s[t] = v;
    __syncthreads();
    for (int off = 1; off < 256; off <<= 1) {
        int u = (t >= off) ? s[t - off] : 0;
        __syncthreads();
        s[t] += u;
        __syncthreads();
    }
    if (t < SCAN_BLOCKS) g_blocksum[t] = s[t] - v;
}

__global__ void scanC_kernel() {
    int idx = blockIdx.x * 256 + threadIdx.x;
    if (idx < N_NODES) g_cur[idx] += g_blocksum[blockIdx.x];
}

__global__ void scatter_kernel(const int* __restrict__ ei, const float* __restrict__ ea) {
    int t = blockIdx.x * blockDim.x + threadIdx.x;
    int stride = gridDim.x * blockDim.x;
    for (int e = t; e < N_EDGES; e += stride) {
        int src = __ldg(&ei[e]);
        int dst = __ldg(&ei[N_EDGES + e]);
        float a0 = __ldg(&ea[e * 3 + 0]);
        float a1 = __ldg(&ea[e * 3 + 1]);
        float a2 = __ldg(&ea[e * 3 + 2]);
        int p = atomicAdd(&g_cur[src], 1);
        g_e4[p] = make_int4(src, dst, __float_as_int(a0), __float_as_int(a1));
        g_ea2[p] = a2;
    }
}

// ---------------- per-edge MLP precompute: h[26] packed fp16, 64 B/edge ----------------
__global__ void hcomp_kernel(const float* __restrict__ Wa, const float* __restrict__ sc,
                             __half* __restrict__ H) {
    __shared__ float4 kpar[MLP_HID];   // {wa0*s, wa1*s, wa2*s, c}
    if (threadIdx.x < MLP_HID) {
        int k = threadIdx.x;
        float s = __ldg(&sc[k]);
        kpar[k] = make_float4(__ldg(&Wa[k]) * s, __ldg(&Wa[25 + k]) * s,
                              __ldg(&Wa[50 + k]) * s, __ldg(&sc[MLP_HID + k]));
    }
    __syncthreads();

    int e = blockIdx.x * blockDim.x + threadIdx.x;   // exact: 800000 / 256 = 3125 blocks
    if (e >= N_EDGES) return;
    const int4 q4 = __ldg(&g_e4[e]);
    const float a0 = __int_as_float(q4.z);
    const float a1 = __int_as_float(q4.w);
    const float a2 = __ldg(&g_ea2[e]);

    float hv[26];
#pragma unroll
    for (int k = 0; k < MLP_HID; k++) {
        const float4 w = kpar[k];
        hv[k] = fmaxf(fmaf(a2, w.z, fmaf(a1, w.y, fmaf(a0, w.x, w.w))), 0.f);
    }
    hv[25] = 1.0f;   // bias row

    unsigned int wrds[13];
#pragma unroll
    for (int j = 0; j < 13; j++) {
        __half2 p = __floats2half2_rn(hv[2 * j], hv[2 * j + 1]);
        wrds[j] = *(const unsigned int*)&p;
    }
    uint4* Hp = (uint4*)(H + (size_t)e * HROW);
    Hp[0] = make_uint4(wrds[0], wrds[1], wrds[2], wrds[3]);
    Hp[1] = make_uint4(wrds[4], wrds[5], wrds[6], wrds[7]);
    Hp[2] = make_uint4(wrds[8], wrds[9], wrds[10], wrds[11]);
    Hp[3] = make_uint4(wrds[12], 0u, 0u, 0u);
}

// ---------------- per-node precompute (HFMA2): P[n,k,o] = sum_i x[n,i]*Wb[k,i*16+o]
__global__ void pk_kernel(const float* __restrict__ x, const float* __restrict__ Wb,
                          const float* __restrict__ bb, __half* __restrict__ P) {
    __shared__ __half2 Wbs[KROWS * 128];   // [k][i*8 + c2], 13.3 KB; row 25 = bb
    for (int idx = threadIdx.x; idx < KROWS * 128; idx += blockDim.x) {
        int k = idx >> 7, rem = idx & 127;
        int i = rem >> 3, c2 = rem & 7;
        const float* srcrow = (k < MLP_HID) ? (Wb + k * 256) : bb;
        Wbs[idx] = __floats2half2_rn(srcrow[i * 16 + c2 * 2], srcrow[i * 16 + c2 * 2 + 1]);
    }
    __syncthreads();

    int t = blockIdx.x * blockDim.x + threadIdx.x;
    int n0 = (t >> 2) * 2;
    int cg = t & 3;
    if (n0 >= N_NODES) return;

    const float4* xrow0 = (const float4*)(x + n0 * C);
    const float4* xrow1 = (const float4*)(x + (n0 + 1) * C);
    float4 q0[4] = {__ldg(xrow0+0), __ldg(xrow0+1), __ldg(xrow0+2), __ldg(xrow0+3)};
    float4 q1[4] = {__ldg(xrow1+0), __ldg(xrow1+1), __ldg(xrow1+2), __ldg(xrow1+3)};
    const float* xf0 = (const float*)q0;
    const float* xf1 = (const float*)q1;
    __half2 xh0[16], xh1[16];
#pragma unroll
    for (int i = 0; i < 16; i++) {
        xh0[i] = __half2half2(__float2half_rn(xf0[i]));
        xh1[i] = __half2half2(__float2half_rn(xf1[i]));
    }

    __half* Pout0 = P + (size_t)n0 * PROW_PAD;
    __half* Pout1 = Pout0 + PROW_PAD;
#pragma unroll
    for (int k = 0; k < KROWS; k++) {
        __half2 a00 = __float2half2_rn(0.f), a01 = a00, a10 = a00, a11 = a00;
        const __half2* wrow = &Wbs[k * 128 + cg * 2];
#pragma unroll
        for (int i = 0; i < 16; i++) {
            __half2 w0 = wrow[i * 8];
            __half2 w1 = wrow[i * 8 + 1];
            a00 = __hfma2(xh0[i], w0, a00);
            a01 = __hfma2(xh0[i], w1, a01);
            a10 = __hfma2(xh1[i], w0, a10);
            a11 = __hfma2(xh1[i], w1, a11);
        }
        *(uint2*)(Pout0 + k * 16 + cg * 4) =
            make_uint2(*(const unsigned int*)&a00, *(const unsigned int*)&a01);
        *(uint2*)(Pout1 + k * 16 + cg * 4) =
            make_uint2(*(const unsigned int*)&a10, *(const unsigned int*)&a11);
    }
}

// ---------------- edge kernel: src-sorted, fp16 P, precomputed fp16 h, 2 lanes/edge ----------------
__global__ void __launch_bounds__(256, 5) edge_kernel(
        const __half* __restrict__ H, const __half* __restrict__ P,
        float* __restrict__ agg) {
    const int h8 = threadIdx.x & 1;                 // which 8-col half
    const int estride = (gridDim.x * blockDim.x) >> 1;
    for (int e = (blockIdx.x * blockDim.x + threadIdx.x) >> 1; e < N_EDGES; e += estride) {
        const int2 sd = __ldg((const int2*)&g_e4[e]);
        const int src = sd.x;
        const int dst = sd.y;

        // load packed h[0..25] (both lanes same addresses -> L1 dedup)
        const uint4* Hp = (const uint4*)(H + (size_t)e * HROW);
        const uint4 hA = __ldg(Hp + 0);   // k 0-7
        const uint4 hB = __ldg(Hp + 1);   // k 8-15
        const uint4 hC = __ldg(Hp + 2);   // k 16-23
        const unsigned int hD = __ldg((const unsigned int*)(H + (size_t)e * HROW + 24)); // k 24-25
        const unsigned int hw[13] = {hA.x, hA.y, hA.z, hA.w, hB.x, hB.y, hB.z, hB.w,
                                     hC.x, hC.y, hC.z, hC.w, hD};

        const uint4* __restrict__ Pp = (const uint4*)(P + (size_t)src * PROW_PAD) + h8;
        __half2 acc0 = __float2half2_rn(0.f), acc1 = acc0, acc2 = acc0, acc3 = acc0;

#pragma unroll
        for (int j = 0; j < 13; j++) {
            const unsigned int w = hw[j];
            if (w & 0xFFFFu) {        // h[2j] != 0 (relu clamps to +0)
                const __half2 hh = __low2half2(*(const __half2*)&w);
                const uint4 q = __ldg(Pp + (2 * j) * 2);
                acc0 = __hfma2(hh, *(const __half2*)&q.x, acc0);
                acc1 = __hfma2(hh, *(const __half2*)&q.y, acc1);
                acc2 = __hfma2(hh, *(const __half2*)&q.z, acc2);
                acc3 = __hfma2(hh, *(const __half2*)&q.w, acc3);
            }
            if (w >> 16) {            // h[2j+1] != 0 (j=12: k=25 bias row, h=1)
                const __half2 hh = __high2half2(*(const __half2*)&w);
                const uint4 q = __ldg(Pp + (2 * j + 1) * 2);
                acc0 = __hfma2(hh, *(const __half2*)&q.x, acc0);
                acc1 = __hfma2(hh, *(const __half2*)&q.y, acc1);
                acc2 = __hfma2(hh, *(const __half2*)&q.z, acc2);
                acc3 = __hfma2(hh, *(const __half2*)&q.w, acc3);
            }
        }

        const float2 f0 = __half22float2(acc0);
        const float2 f1 = __half22float2(acc1);
        const float2 f2 = __half22float2(acc2);
        const float2 f3 = __half22float2(acc3);

        float* addr = &agg[dst * C + h8 * 8];
        asm volatile("red.global.add.v4.f32 [%0], {%1,%2,%3,%4};"
                     :: "l"(addr), "f"(f0.x), "f"(f0.y), "f"(f1.x), "f"(f1.y)
                     : "memory");
        asm volatile("red.global.add.v4.f32 [%0], {%1,%2,%3,%4};"
                     :: "l"(addr + 4), "f"(f2.x), "f"(f2.y), "f"(f3.x), "f"(f3.y)
                     : "memory");
    }
}

// ---------------- node kernel: SHUFFLE-FREE. 4 lanes per node.
__global__ void node_kernel(const float* __restrict__ agg, const float* __restrict__ deg,
                            const float* __restrict__ xin, const float* __restrict__ root,
                            const float* __restrict__ bias, float* __restrict__ xout,
                            const int* __restrict__ batch, float* __restrict__ pooled,
                            float* __restrict__ cnt) {
    __shared__ float4 root_s[16][4];
    __shared__ float4 bias_s[4];
    if (threadIdx.x < 64) {
        int i = threadIdx.x >> 2, cgi = threadIdx.x & 3;
        root_s[i][cgi] = ((const float4*)(root + i * 16))[cgi];
        if (i == 0) bias_s[cgi] = ((const float4*)bias)[cgi];
    }
    __syncthreads();

    int t = blockIdx.x * blockDim.x + threadIdx.x;
    int n = t >> 2;
    int cg = t & 3;
    if (n >= N_NODES) return;

    const float dinv = 1.0f / fmaxf(deg[n], 1.0f);
    float4 a = ((const float4*)(agg + n * C))[cg];
    float4 v = make_float4(a.x * dinv, a.y * dinv, a.z * dinv, a.w * dinv);

    const float4* xr = (const float4*)(xin + n * C);
    float4 xq[4] = {__ldg(xr + 0), __ldg(xr + 1), __ldg(xr + 2), __ldg(xr + 3)};
    const float* xs = (const float*)xq;
#pragma unroll
    for (int i = 0; i < 16; i++) {
        float4 r = root_s[i][cg];
        v.x = fmaf(xs[i], r.x, v.x);
        v.y = fmaf(xs[i], r.y, v.y);
        v.z = fmaf(xs[i], r.z, v.z);
        v.w = fmaf(xs[i], r.w, v.w);
    }
    float4 b = bias_s[cg];
    v.x += b.x; v.y += b.y; v.z += b.z; v.w += b.w;
    v.x = (v.x > 0.f) ? v.x : expm1f(v.x);
    v.y = (v.y > 0.f) ? v.y : expm1f(v.y);
    v.z = (v.z > 0.f) ? v.z : expm1f(v.z);
    v.w = (v.w > 0.f) ? v.w : expm1f(v.w);

    ((float4*)(xout + n * C))[cg] = v;

    if (batch != nullptr) {
        int g = __ldg(&batch[n]);
        float* addr = &pooled[g * C + cg * 4];
        asm volatile("red.global.add.v4.f32 [%0], {%1,%2,%3,%4};"
                     :: "l"(addr), "f"(v.x), "f"(v.y), "f"(v.z), "f"(v.w)
                     : "memory");
        if (cg == 0) atomicAdd(&cnt[g], 1.0f);
    }
}

// ---------------- head: out = (pooled/cnt) @ fcW + fcb ----------------
__global__ void final_kernel(const float* __restrict__ fcW, const float* __restrict__ fcb,
                             float* __restrict__ out) {
    int t = blockIdx.x * blockDim.x + threadIdx.x;
    if (t >= N_GRAPHS * OUT_C) return;
    int g = t / OUT_C;
    int o = t % OUT_C;
    float c = fmaxf(g_cnt[g], 1.0f);
    float acc = fcb[o];
#pragma unroll
    for (int i = 0; i < 16; i++) acc = fmaf(g_pooled[g * C + i] / c, fcW[i * OUT_C + o], acc);
    out[g * OUT_C + o] = acc;
}

extern "C" void kernel_launch(void* const* d_in, const int* in_sizes, int n_in,
                              void* d_out, int out_size) {
    const float* x     = (const float*)d_in[0];
    const int*   ei    = (const int*)d_in[1];
    const float* ea    = (const float*)d_in[2];
    const int*   batch = (const int*)d_in[3];
    const float* W1a = (const float*)d_in[4],  *b1a = (const float*)d_in[5];
    const float* g1  = (const float*)d_in[6],  *bt1 = (const float*)d_in[7];
    const float* m1  = (const float*)d_in[8],  *v1  = (const float*)d_in[9];
    const float* W1b = (const float*)d_in[10], *b1b = (const float*)d_in[11];
    const float* root1 = (const float*)d_in[12], *bias1 = (const float*)d_in[13];
    const float* W2a = (const float*)d_in[14], *b2a = (const float*)d_in[15];
    const float* g2  = (const float*)d_in[16], *bt2 = (const float*)d_in[17];
    const float* m2  = (const float*)d_in[18], *v2  = (const float*)d_in[19];
    const float* W2b = (const float*)d_in[20], *b2b = (const float*)d_in[21];
    const float* root2 = (const float*)d_in[22], *bias2 = (const float*)d_in[23];
    const float* fcW = (const float*)d_in[24], *fcb = (const float*)d_in[25];
    float* out = (float*)d_out;

    zero_kernel<<<512, 256>>>();
    prep_kernel<<<1, 32>>>(b1a, g1, bt1, m1, v1, b2a, g2, bt2, m2, v2);

    // ---- counting sort of edges by src (parallel scan) ----
    hist_kernel<<<592, 256>>>(ei);
    scanA_kernel<<<SCAN_BLOCKS, 256>>>();
    scanB_kernel<<<1, 256>>>();
    scanC_kernel<<<SCAN_BLOCKS, 256>>>();
    scatter_kernel<<<592, 256>>>(ei, ea);

    __half* P = nullptr; cudaGetSymbolAddress((void**)&P, g_Ph);
    __half* H = nullptr; cudaGetSymbolAddress((void**)&H, g_h);
    float* aggA = nullptr; cudaGetSymbolAddress((void**)&aggA, g_aggA);
    float* aggB = nullptr; cudaGetSymbolAddress((void**)&aggB, g_aggB);
    float* deg = nullptr; cudaGetSymbolAddress((void**)&deg, g_deg);
    float* x1 = nullptr; cudaGetSymbolAddress((void**)&x1, g_x1);
    float* pooled = nullptr; cudaGetSymbolAddress((void**)&pooled, g_pooled);
    float* cnt = nullptr; cudaGetSymbolAddress((void**)&cnt, g_cnt);
    float* sc1 = nullptr; cudaGetSymbolAddress((void**)&sc1, g_sc1);
    float* sc2 = nullptr; cudaGetSymbolAddress((void**)&sc2, g_sc2);

    const int PK_GRID = (N_NODES / 2 * 4 + 255) / 256;   // 2 nodes/thread, 4 lanes/node-pair
    const int HC_GRID = N_EDGES / 256;                    // 3125, exact
    const int EDGE_GRID = 148 * 5;                        // persistent, 5 CTAs/SM
    const int NODE_GRID = (N_NODES * 4 + 255) / 256;      // 4 lanes/node

    // ---- layer 1 ----
    hcomp_kernel<<<HC_GRID, 256>>>(W1a, sc1, H);
    pk_kernel<<<PK_GRID, 256>>>(x, W1b, b1b, P);
    edge_kernel<<<EDGE_GRID, 256>>>(H, P, aggA);
    node_kernel<<<NODE_GRID, 256>>>(aggA, deg, x, root1, bias1, x1,
                                    nullptr, nullptr, nullptr);

    // ---- layer 2 ----
    hcomp_kernel<<<HC_GRID, 256>>>(W2a, sc2, H);
    pk_kernel<<<PK_GRID, 256>>>(x1, W2b, b2b, P);
    edge_kernel<<<EDGE_GRID, 256>>>(H, P, aggB);
    node_kernel<<<NODE_GRID, 256>>>(aggB, deg, x1, root2, bias2, x1,
                                    batch, pooled, cnt);

    // ---- head ----
    final_kernel<<<(N_GRAPHS * OUT_C + 255) / 256, 256>>>(fcW, fcb, out);
}

// round 16
// speedup vs baseline: 1.2977x; 1.2977x over previous
#include <cuda_runtime.h>
#include <cuda_fp16.h>
#include <cstdint>
#include <math.h>

#define N_NODES 50000
#define N_EDGES 800000
#define N_GRAPHS 500
#define C 16            // IN_C == HID_C == 16
#define OUT_C 10
#define MLP_HID 25
#define KROWS 26        // 25 MLP rows + 1 bias row (always weight 1)
#define PROW_PAD 448    // padded to 896 B = 7 x 128B lines per node
#define SCAN_BLOCKS ((N_NODES + 255) / 256)   // 196

// ---------------- scratch (static device globals; no allocs allowed) ----------------
__device__ __align__(128) __half g_Ph[(size_t)N_NODES * PROW_PAD];   // 44.8 MB, fits L2
__device__ __align__(16) float g_aggA[N_NODES * C];
__device__ __align__(16) float g_aggB[N_NODES * C];
__device__ float g_deg[N_NODES];
__device__ __align__(16) float g_x1[N_NODES * C];
__device__ __align__(16) float g_pooled[N_GRAPHS * C];
__device__ float g_cnt[N_GRAPHS];
__device__ float g_sc1[2 * MLP_HID];
__device__ float g_sc2[2 * MLP_HID];
// edge sort scratch
__device__ int g_srccnt[N_NODES];
__device__ int g_cur[N_NODES];
__device__ int g_blocksum[SCAN_BLOCKS];
__device__ __align__(16) int4 g_e4[N_EDGES];    // {src, dst, a0bits, a1bits}
__device__ float g_ea2[N_EDGES];                // a2

// ---------------- zero scratch ----------------
__global__ void zero_kernel() {
    int t = blockIdx.x * blockDim.x + threadIdx.x;
    int stride = gridDim.x * blockDim.x;
    const int NA = N_NODES * C;
    for (int i = t; i < NA; i += stride) { g_aggA[i] = 0.f; g_aggB[i] = 0.f; }
    for (int i = t; i < N_NODES; i += stride) { g_deg[i] = 0.f; g_srccnt[i] = 0; }
    for (int i = t; i < N_GRAPHS * C; i += stride) g_pooled[i] = 0.f;
    for (int i = t; i < N_GRAPHS; i += stride) g_cnt[i] = 0.f;
}

// ---------------- fold BatchNorm(eval) into affine: h = relu(s*dot + c) ----------------
__global__ void prep_kernel(const float* __restrict__ b1a, const float* __restrict__ g1,
                            const float* __restrict__ bt1, const float* __restrict__ m1,
                            const float* __restrict__ v1,
                            const float* __restrict__ b2a, const float* __restrict__ g2,
                            const float* __restrict__ bt2, const float* __restrict__ m2,
                            const float* __restrict__ v2) {
    int k = threadIdx.x;
    if (k < MLP_HID) {
        float s1 = g1[k] * rsqrtf(v1[k] + 1e-5f);
        g_sc1[k] = s1;
        g_sc1[MLP_HID + k] = s1 * (b1a[k] - m1[k]) + bt1[k];
        float s2 = g2[k] * rsqrtf(v2[k] + 1e-5f);
        g_sc2[k] = s2;
        g_sc2[MLP_HID + k] = s2 * (b2a[k] - m2[k]) + bt2[k];
    }
}

// ---------------- counting sort of edges by src ----------------
__global__ void hist_kernel(const int* __restrict__ ei) {
    int t = blockIdx.x * blockDim.x + threadIdx.x;
    int stride = gridDim.x * blockDim.x;
    for (int e = t; e < N_EDGES; e += stride) {
        atomicAdd(&g_srccnt[__ldg(&ei[e])], 1);
        atomicAdd(&g_deg[__ldg(&ei[N_EDGES + e])], 1.0f);
    }
}

__global__ void scanA_kernel() {
    __shared__ int s[256];
    int t = threadIdx.x;
    int idx = blockIdx.x * 256 + t;
    int v = (idx < N_NODES) ? g_srccnt[idx] : 0;
    s[t] = v;
    __syncthreads();
    for (int off = 1; off < 256; off <<= 1) {
        int u = (t >= off) ? s[t - off] : 0;
        __syncthreads();
        s[t] += u;
        __syncthreads();
    }
    if (idx < N_NODES) g_cur[idx] = s[t] - v;
    if (t == 255) g_blocksum[blockIdx.x] = s[255];
}

__global__ void scanB_kernel() {
    __shared__ int s[256];
    int t = threadIdx.x;
    int v = (t < SCAN_BLOCKS) ? g_blocksum[t] : 0;
    s[t] = v;
    __syncthreads();
    for (int off = 1; off < 256; off <<= 1) {
        int u = (t >= off) ? s[t - off] : 0;
        __syncthreads();
        s[t] += u;
        __syncthreads();
    }
    if (t < SCAN_BLOCKS) g_blocksum[t] = s[t] - v;
}

__global__ void scanC_kernel() {
    int idx = blockIdx.x * 256 + threadIdx.x;
    if (idx < N_NODES) g_cur[idx] += g_blocksum[blockIdx.x];
}

__global__ void scatter_kernel(const int* __restrict__ ei, const float* __restrict__ ea) {
    int t = blockIdx.x * blockDim.x + threadIdx.x;
    int stride = gridDim.x * blockDim.x;
    for (int e = t; e < N_EDGES; e += stride) {
        int src = __ldg(&ei[e]);
        int dst = __ldg(&ei[N_EDGES + e]);
        float a0 = __ldg(&ea[e * 3 + 0]);
        float a1 = __ldg(&ea[e * 3 + 1]);
        float a2 = __ldg(&ea[e * 3 + 2]);
        int p = atomicAdd(&g_cur[src], 1);
        g_e4[p] = make_int4(src, dst, __float_as_int(a0), __float_as_int(a1));
        g_ea2[p] = a2;
    }
}

// ---------------- per-node precompute (HFMA2): P[n,k,o] = sum_i x[n,i]*Wb[k,i*16+o]
__global__ void pk_kernel(const float* __restrict__ x, const float* __restrict__ Wb,
                          const float* __restrict__ bb, __half* __restrict__ P) {
    __shared__ __half2 Wbs[KROWS * 128];   // [k][i*8 + c2], 13.3 KB; row 25 = bb
    for (int idx = threadIdx.x; idx < KROWS * 128; idx += blockDim.x) {
        int k = idx >> 7, rem = idx & 127;
        int i = rem >> 3, c2 = rem & 7;
        const float* srcrow = (k < MLP_HID) ? (Wb + k * 256) : bb;
        Wbs[idx] = __floats2half2_rn(srcrow[i * 16 + c2 * 2], srcrow[i * 16 + c2 * 2 + 1]);
    }
    __syncthreads();

    int t = blockIdx.x * blockDim.x + threadIdx.x;
    int n0 = (t >> 2) * 2;
    int cg = t & 3;
    if (n0 >= N_NODES) return;

    const float4* xrow0 = (const float4*)(x + n0 * C);
    const float4* xrow1 = (const float4*)(x + (n0 + 1) * C);
    float4 q0[4] = {__ldg(xrow0+0), __ldg(xrow0+1), __ldg(xrow0+2), __ldg(xrow0+3)};
    float4 q1[4] = {__ldg(xrow1+0), __ldg(xrow1+1), __ldg(xrow1+2), __ldg(xrow1+3)};
    const float* xf0 = (const float*)q0;
    const float* xf1 = (const float*)q1;
    __half2 xh0[16], xh1[16];
#pragma unroll
    for (int i = 0; i < 16; i++) {
        xh0[i] = __half2half2(__float2half_rn(xf0[i]));
        xh1[i] = __half2half2(__float2half_rn(xf1[i]));
    }

    __half* Pout0 = P + (size_t)n0 * PROW_PAD;
    __half* Pout1 = Pout0 + PROW_PAD;
#pragma unroll
    for (int k = 0; k < KROWS; k++) {
        __half2 a00 = __float2half2_rn(0.f), a01 = a00, a10 = a00, a11 = a00;
        const __half2* wrow = &Wbs[k * 128 + cg * 2];
#pragma unroll
        for (int i = 0; i < 16; i++) {
            __half2 w0 = wrow[i * 8];
            __half2 w1 = wrow[i * 8 + 1];
            a00 = __hfma2(xh0[i], w0, a00);
            a01 = __hfma2(xh0[i], w1, a01);
            a10 = __hfma2(xh1[i], w0, a10);
            a11 = __hfma2(xh1[i], w1, a11);
        }
        *(uint2*)(Pout0 + k * 16 + cg * 4) =
            make_uint2(*(const unsigned int*)&a00, *(const unsigned int*)&a01);
        *(uint2*)(Pout1 + k * 16 + cg * 4) =
            make_uint2(*(const unsigned int*)&a10, *(const unsigned int*)&a11);
    }
}

// ---------------- edge kernel: src-sorted, fp16 P, 2 lanes/edge, ILP-2 (two sorted halves) ----------------
__global__ void __launch_bounds__(256, 4) edge_kernel(
        const float* __restrict__ Wa, const float* __restrict__ sc,
        const __half* __restrict__ P, float* __restrict__ agg) {
    __shared__ float4 kpar[MLP_HID];   // {wa0*s, wa1*s, wa2*s, c}  -> h = 3 chained FMAs
    if (threadIdx.x < MLP_HID) {
        int k = threadIdx.x;
        float s = __ldg(&sc[k]);
        kpar[k] = make_float4(__ldg(&Wa[k]) * s, __ldg(&Wa[25 + k]) * s,
                              __ldg(&Wa[50 + k]) * s, __ldg(&sc[MLP_HID + k]));
    }
    __syncthreads();

    const int h8 = threadIdx.x & 1;                 // which 8-col half
    const int HALF = N_EDGES / 2;
    const int estride = (gridDim.x * blockDim.x) >> 1;
    for (int e = (blockIdx.x * blockDim.x + threadIdx.x) >> 1; e < HALF; e += estride) {
        const int eB = e + HALF;
        const int4 qA = __ldg(&g_e4[e]);
        const int4 qB = __ldg(&g_e4[eB]);
        const float a0A = __int_as_float(qA.z), a1A = __int_as_float(qA.w);
        const float a0B = __int_as_float(qB.z), a1B = __int_as_float(qB.w);
        const float a2A = __ldg(&g_ea2[e]);
        const float a2B = __ldg(&g_ea2[eB]);

        const uint4* __restrict__ PpA = (const uint4*)(P + (size_t)qA.x * PROW_PAD) + h8;
        const uint4* __restrict__ PpB = (const uint4*)(P + (size_t)qB.x * PROW_PAD) + h8;

        // acc init = bias row (k=25), weight 1
        __half2 accA0, accA1, accA2, accA3, accB0, accB1, accB2, accB3;
        {
            const uint4 qa = __ldg(PpA + 25 * 2);
            const uint4 qb = __ldg(PpB + 25 * 2);
            accA0 = *(const __half2*)&qa.x; accA1 = *(const __half2*)&qa.y;
            accA2 = *(const __half2*)&qa.z; accA3 = *(const __half2*)&qa.w;
            accB0 = *(const __half2*)&qb.x; accB1 = *(const __half2*)&qb.y;
            accB2 = *(const __half2*)&qb.z; accB3 = *(const __half2*)&qb.w;
        }

#pragma unroll
        for (int k = 0; k < MLP_HID; k++) {
            const float4 w = kpar[k];
            const float hA = fmaf(a2A, w.z, fmaf(a1A, w.y, fmaf(a0A, w.x, w.w)));
            const float hB = fmaf(a2B, w.z, fmaf(a1B, w.y, fmaf(a0B, w.x, w.w)));
            if (hA > 0.f) {
                const __half2 hh = __float2half2_rn(hA);
                const uint4 q = __ldg(PpA + k * 2);
                accA0 = __hfma2(hh, *(const __half2*)&q.x, accA0);
                accA1 = __hfma2(hh, *(const __half2*)&q.y, accA1);
                accA2 = __hfma2(hh, *(const __half2*)&q.z, accA2);
                accA3 = __hfma2(hh, *(const __half2*)&q.w, accA3);
            }
            if (hB > 0.f) {
                const __half2 hh = __float2half2_rn(hB);
                const uint4 q = __ldg(PpB + k * 2);
                accB0 = __hfma2(hh, *(const __half2*)&q.x, accB0);
                accB1 = __hfma2(hh, *(const __half2*)&q.y, accB1);
                accB2 = __hfma2(hh, *(const __half2*)&q.z, accB2);
                accB3 = __hfma2(hh, *(const __half2*)&q.w, accB3);
            }
        }

        {
            const float2 f0 = __half22float2(accA0);
            const float2 f1 = __half22float2(accA1);
            const float2 f2 = __half22float2(accA2);
            const float2 f3 = __half22float2(accA3);
            float* addr = &agg[qA.y * C + h8 * 8];
            asm volatile("red.global.add.v4.f32 [%0], {%1,%2,%3,%4};"
                         :: "l"(addr), "f"(f0.x), "f"(f0.y), "f"(f1.x), "f"(f1.y)
                         : "memory");
            asm volatile("red.global.add.v4.f32 [%0], {%1,%2,%3,%4};"
                         :: "l"(addr + 4), "f"(f2.x), "f"(f2.y), "f"(f3.x), "f"(f3.y)
                         : "memory");
        }
        {
            const float2 f0 = __half22float2(accB0);
            const float2 f1 = __half22float2(accB1);
            const float2 f2 = __half22float2(accB2);
            const float2 f3 = __half22float2(accB3);
            float* addr = &agg[qB.y * C + h8 * 8];
            asm volatile("red.global.add.v4.f32 [%0], {%1,%2,%3,%4};"
                         :: "l"(addr), "f"(f0.x), "f"(f0.y), "f"(f1.x), "f"(f1.y)
                         : "memory");
            asm volatile("red.global.add.v4.f32 [%0], {%1,%2,%3,%4};"
                         :: "l"(addr + 4), "f"(f2.x), "f"(f2.y), "f"(f3.x), "f"(f3.y)
                         : "memory");
        }
    }
}

// ---------------- node kernel: SHUFFLE-FREE. 4 lanes per node.
__global__ void node_kernel(const float* __restrict__ agg, const float* __restrict__ deg,
                            const float* __restrict__ xin, const float* __restrict__ root,
                            const float* __restrict__ bias, float* __restrict__ xout,
                            const int* __restrict__ batch, float* __restrict__ pooled,
                            float* __restrict__ cnt) {
    __shared__ float4 root_s[16][4];
    __shared__ float4 bias_s[4];
    if (threadIdx.x < 64) {
        int i = threadIdx.x >> 2, cgi = threadIdx.x & 3;
        root_s[i][cgi] = ((const float4*)(root + i * 16))[cgi];
        if (i == 0) bias_s[cgi] = ((const float4*)bias)[cgi];
    }
    __syncthreads();

    int t = blockIdx.x * blockDim.x + threadIdx.x;
    int n = t >> 2;
    int cg = t & 3;
    if (n >= N_NODES) return;

    const float dinv = 1.0f / fmaxf(deg[n], 1.0f);
    float4 a = ((const float4*)(agg + n * C))[cg];
    float4 v = make_float4(a.x * dinv, a.y * dinv, a.z * dinv, a.w * dinv);

    const float4* xr = (const float4*)(xin + n * C);
    float4 xq[4] = {__ldg(xr + 0), __ldg(xr + 1), __ldg(xr + 2), __ldg(xr + 3)};
    const float* xs = (const float*)xq;
#pragma unroll
    for (int i = 0; i < 16; i++) {
        float4 r = root_s[i][cg];
        v.x = fmaf(xs[i], r.x, v.x);
        v.y = fmaf(xs[i], r.y, v.y);
        v.z = fmaf(xs[i], r.z, v.z);
        v.w = fmaf(xs[i], r.w, v.w);
    }
    float4 b = bias_s[cg];
    v.x += b.x; v.y += b.y; v.z += b.z; v.w += b.w;
    v.x = (v.x > 0.f) ? v.x : expm1f(v.x);
    v.y = (v.y > 0.f) ? v.y : expm1f(v.y);
    v.z = (v.z > 0.f) ? v.z : expm1f(v.z);
    v.w = (v.w > 0.f) ? v.w : expm1f(v.w);

    ((float4*)(xout + n * C))[cg] = v;

    if (batch != nullptr) {
        int g = __ldg(&batch[n]);
        float* addr = &pooled[g * C + cg * 4];
        asm volatile("red.global.add.v4.f32 [%0], {%1,%2,%3,%4};"
                     :: "l"(addr), "f"(v.x), "f"(v.y), "f"(v.z), "f"(v.w)
                     : "memory");
        if (cg == 0) atomicAdd(&cnt[g], 1.0f);
    }
}

// ---------------- head: out = (pooled/cnt) @ fcW + fcb ----------------
__global__ void final_kernel(const float* __restrict__ fcW, const float* __restrict__ fcb,
                             float* __restrict__ out) {
    int t = blockIdx.x * blockDim.x + threadIdx.x;
    if (t >= N_GRAPHS * OUT_C) return;
    int g = t / OUT_C;
    int o = t % OUT_C;
    float c = fmaxf(g_cnt[g], 1.0f);
    float acc = fcb[o];
#pragma unroll
    for (int i = 0; i < 16; i++) acc = fmaf(g_pooled[g * C + i] / c, fcW[i * OUT_C + o], acc);
    out[g * OUT_C + o] = acc;
}

extern "C" void kernel_launch(void* const* d_in, const int* in_sizes, int n_in,
                              void* d_out, int out_size) {
    const float* x     = (const float*)d_in[0];
    const int*   ei    = (const int*)d_in[1];
    const float* ea    = (const float*)d_in[2];
    const int*   batch = (const int*)d_in[3];
    const float* W1a = (const float*)d_in[4],  *b1a = (const float*)d_in[5];
    const float* g1  = (const float*)d_in[6],  *bt1 = (const float*)d_in[7];
    const float* m1  = (const float*)d_in[8],  *v1  = (const float*)d_in[9];
    const float* W1b = (const float*)d_in[10], *b1b = (const float*)d_in[11];
    const float* root1 = (const float*)d_in[12], *bias1 = (const float*)d_in[13];
    const float* W2a = (const float*)d_in[14], *b2a = (const float*)d_in[15];
    const float* g2  = (const float*)d_in[16], *bt2 = (const float*)d_in[17];
    const float* m2  = (const float*)d_in[18], *v2  = (const float*)d_in[19];
    const float* W2b = (const float*)d_in[20], *b2b = (const float*)d_in[21];
    const float* root2 = (const float*)d_in[22], *bias2 = (const float*)d_in[23];
    const float* fcW = (const float*)d_in[24], *fcb = (const float*)d_in[25];
    float* out = (float*)d_out;

    zero_kernel<<<512, 256>>>();
    prep_kernel<<<1, 32>>>(b1a, g1, bt1, m1, v1, b2a, g2, bt2, m2, v2);

    // ---- counting sort of edges by src (parallel scan) ----
    hist_kernel<<<592, 256>>>(ei);
    scanA_kernel<<<SCAN_BLOCKS, 256>>>();
    scanB_kernel<<<1, 256>>>();
    scanC_kernel<<<SCAN_BLOCKS, 256>>>();
    scatter_kernel<<<592, 256>>>(ei, ea);

    __half* P = nullptr; cudaGetSymbolAddress((void**)&P, g_Ph);
    float* aggA = nullptr; cudaGetSymbolAddress((void**)&aggA, g_aggA);
    float* aggB = nullptr; cudaGetSymbolAddress((void**)&aggB, g_aggB);
    float* deg = nullptr; cudaGetSymbolAddress((void**)&deg, g_deg);
    float* x1 = nullptr; cudaGetSymbolAddress((void**)&x1, g_x1);
    float* pooled = nullptr; cudaGetSymbolAddress((void**)&pooled, g_pooled);
    float* cnt = nullptr; cudaGetSymbolAddress((void**)&cnt, g_cnt);
    float* sc1 = nullptr; cudaGetSymbolAddress((void**)&sc1, g_sc1);
    float* sc2 = nullptr; cudaGetSymbolAddress((void**)&sc2, g_sc2);

    const int PK_GRID = (N_NODES / 2 * 4 + 255) / 256;   // 2 nodes/thread, 4 lanes/node-pair
    const int EDGE_GRID = 148 * 4;                        // persistent, 4 CTAs/SM
    const int NODE_GRID = (N_NODES * 4 + 255) / 256;      // 4 lanes/node

    // ---- layer 1 ----
    pk_kernel<<<PK_GRID, 256>>>(x, W1b, b1b, P);
    edge_kernel<<<EDGE_GRID, 256>>>(W1a, sc1, P, aggA);
    node_kernel<<<NODE_GRID, 256>>>(aggA, deg, x, root1, bias1, x1,
                                    nullptr, nullptr, nullptr);

    // ---- layer 2 ----
    pk_kernel<<<PK_GRID, 256>>>(x1, W2b, b2b, P);
    edge_kernel<<<EDGE_GRID, 256>>>(W2a, sc2, P, aggB);
    node_kernel<<<NODE_GRID, 256>>>(aggB, deg, x1, root2, bias2, x1,
                                    batch, pooled, cnt);

    // ---- head ----
    final_kernel<<<(N_GRAPHS * OUT_C + 255) / 256, 256>>>(fcW, fcb, out);
}